// round 17
// baseline (speedup 1.0000x reference)
#include <cuda_runtime.h>
#include <cuda_fp16.h>
#include <math.h>
#include <cstdint>

#define NA 20000
#define NP 50000
#define EMAX 300000
#define DD 256
#define NH 8
#define DKH 32

// ---------------- scratch ----------------
__device__ __half g_Har[NA * DD];
__device__ __half g_Hpr[NP * DD];
__device__ __half g_K0[NA * DD];
__device__ __half g_V0[NA * DD];
__device__ float g_Qa[NA * DD];
__device__ __half g_Kp[NP * DD];
__device__ __half g_Vp[NP * DD];
__device__ float g_Qp[NP * DD];
__device__ float g_Qpc[NP * DD];
__device__ __half g_aggPw[NP * DD];
__device__ __half g_aggPc[NP * DD];
__device__ __half g_aggAc[NA * DD];
__device__ __half g_fW[6 * DD * DD];
__device__ float g_fB[4 * DD];
__device__ __half g_rw[4 * DD * DD];
__device__ int g_deg0[NP];
__device__ int g_deg1[NP];
__device__ int g_deg2[NA];
__device__ int g_rp0[NP + 1];
__device__ int g_rp1[NP + 1];
__device__ int g_rp2[NA + 1];
__device__ int g_cur0[NP];
__device__ int g_cur1[NP];
__device__ int g_cur2[NA];
__device__ int g_col0[EMAX];
__device__ int g_col1[EMAX];
__device__ int g_col2[EMAX];
__device__ int g_psum[64];

// ---------------- fused float->half copy (6 regions) + degree zeroing ----------------
__global__ void halfcopy_zero(
    const float* __restrict__ s0, __half* __restrict__ d0, int n0,
    const float* __restrict__ s1, __half* __restrict__ d1, int n1,
    const float* __restrict__ s2, __half* __restrict__ d2, int n2,
    const float* __restrict__ s3, __half* __restrict__ d3, int n3,
    const float* __restrict__ s4, __half* __restrict__ d4, int n4,
    const float* __restrict__ s5, __half* __restrict__ d5, int n5,
    int* __restrict__ z0, int* __restrict__ z1, int* __restrict__ z2) {
    int i = blockIdx.x * blockDim.x + threadIdx.x;
    const float* s;
    __half* d;
    if (i < n0) { s = s0; d = d0; }
    else if ((i -= n0) < n1) { s = s1; d = d1; }
    else if ((i -= n1) < n2) { s = s2; d = d2; }
    else if ((i -= n2) < n3) { s = s3; d = d3; }
    else if ((i -= n3) < n4) { s = s4; d = d4; }
    else if ((i -= n4) < n5) { s = s5; d = d5; }
    else {
        int z = i - n5;
        if (z < NP) { z0[z] = 0; z1[z] = 0; }
        else if ((z -= NP) < NA) z2[z] = 0;
        return;
    }
    const float4* ip = (const float4*)(s + (size_t)i * 8);
    float4 v0 = ip[0], v1 = ip[1];
    __half2 h0 = __floats2half2_rn(v0.x, v0.y);
    __half2 h1 = __floats2half2_rn(v0.z, v0.w);
    __half2 h2 = __floats2half2_rn(v1.x, v1.y);
    __half2 h3 = __floats2half2_rn(v1.z, v1.w);
    uint4 o;
    o.x = *(uint32_t*)&h0; o.y = *(uint32_t*)&h1; o.z = *(uint32_t*)&h2; o.w = *(uint32_t*)&h3;
    *(uint4*)(d + (size_t)i * 8) = o;
}

// ---------------- fused weight folds (6 variants) + edge histogram ----------------
__global__ void fold_hist(const float* __restrict__ k_w, const float* __restrict__ v_w,
                          const float* __restrict__ q_w, const float* __restrict__ a_w,
                          const float* __restrict__ k_b, const float* __restrict__ v_b,
                          const float* __restrict__ q_b,
                          const float* __restrict__ rel_att, const float* __restrict__ rel_msg,
                          __half* __restrict__ fWk0, __half* __restrict__ fWv0,
                          __half* __restrict__ fWqa, __half* __restrict__ fWaw,
                          __half* __restrict__ fWqc, __half* __restrict__ fWac,
                          float* __restrict__ fBk0, float* __restrict__ fBv0,
                          float* __restrict__ fBqa, float* __restrict__ fBqc,
                          const int* __restrict__ dw, const int* __restrict__ dc,
                          const int* __restrict__ db, int E,
                          int* __restrict__ hd0, int* __restrict__ hd1, int* __restrict__ hd2) {
    const int bb = blockIdx.x;
    if (bb >= 1536) {
        int i = (bb - 1536) * 256 + threadIdx.x;
        if (i < E) atomicAdd(&hd0[dw[i]], 1);
        else if (i < 2 * E) atomicAdd(&hd1[dc[i - E]], 1);
        else if (i < 3 * E) atomicAdd(&hd2[db[i - 2 * E]], 1);
        return;
    }
    const int which = bb >> 8;
    int c = bb & 255, d = threadIdx.x;
    int h = c >> 5, x = c & 31;
    if (which == 3 || which == 5) {
        const float* rel = (which == 3) ? rel_msg + 2 * 8192 : rel_msg + 8192;
        const float* W = (which == 3) ? a_w : a_w + 65536;
        __half* Wout = (which == 3) ? fWaw : fWac;
        float s = 0.f;
#pragma unroll
        for (int i = 0; i < 32; i++)
            s += rel[c * 32 + i] * W[d * DD + h * 32 + i];
        Wout[d * DD + c] = __float2half_rn(s);
        return;
    }
    const float *W, *rel, *b;
    __half* Wout;
    float* bout;
    if (which == 0) { W = k_w; rel = rel_att; b = k_b; Wout = fWk0; bout = fBk0; }
    else if (which == 1) { W = v_w; rel = rel_msg; b = v_b; Wout = fWv0; bout = fBv0; }
    else if (which == 2) { W = q_w; rel = rel_att + 2 * 8192; b = q_b; Wout = fWqa; bout = fBqa; }
    else { W = q_w + 65536; rel = rel_att + 8192; b = q_b + 256; Wout = fWqc; bout = fBqc; }
    float s = 0.f;
    if (which < 2) {
#pragma unroll
        for (int i = 0; i < 32; i++)
            s += rel[(h * 32 + i) * 32 + x] * W[(h * 32 + i) * DD + d];
    } else {
#pragma unroll
        for (int j = 0; j < 32; j++)
            s += rel[(h * 32 + x) * 32 + j] * W[(h * 32 + j) * DD + d];
    }
    Wout[c * DD + d] = __float2half_rn(s);
    if (d == 0) {
        float sb = 0.f;
        if (which < 2) {
#pragma unroll
            for (int i = 0; i < 32; i++)
                sb += rel[(h * 32 + i) * 32 + x] * b[h * 32 + i];
        } else {
#pragma unroll
            for (int j = 0; j < 32; j++)
                sb += rel[(h * 32 + x) * 32 + j] * b[h * 32 + j];
        }
        bout[c] = sb;
    }
}

// ---------------- fp16 mma helpers ----------------
#define SLABH (128 * 40)
#define GSO (4 * SLABH * 2)
#define GS3H (8 * SLABH * 2)

__device__ __forceinline__ void mmah(float c[4], const uint32_t a[4], const uint32_t b[2]) {
    asm volatile(
        "mma.sync.aligned.m16n8k16.row.col.f32.f16.f16.f32 "
        "{%0,%1,%2,%3}, {%4,%5,%6,%7}, {%8,%9}, {%0,%1,%2,%3};"
        : "+f"(c[0]), "+f"(c[1]), "+f"(c[2]), "+f"(c[3])
        : "r"(a[0]), "r"(a[1]), "r"(a[2]), "r"(a[3]), "r"(b[0]), "r"(b[1]));
}

// ---------------- fused out-GEMM: authors 8 slabs, papers 16 slabs (split-K) ----------------
__global__ __launch_bounds__(256) void gemm_out(
    int gaBlocks,
    const __half* __restrict__ Aa, const __half* __restrict__ Ba,
    const __half* __restrict__ Ap1, const __half* __restrict__ Bp1,
    const __half* __restrict__ Ap2, const __half* __restrict__ Bp2,
    const float* __restrict__ biasa, const float* __restrict__ biasp,
    const float* __restrict__ resida, const float* __restrict__ residp,
    const float* __restrict__ skipv,
    float* __restrict__ Ca, float* __restrict__ Cp, int Ma, int Mp) {
    extern __shared__ __half smh[];
    const int tid = threadIdx.x;
    const bool pp = (int)blockIdx.x >= gaBlocks;
    const int m0 = ((int)blockIdx.x - (pp ? gaBlocks : 0)) * 128;
    const int col0 = blockIdx.y * 128;
    const float* bias = pp ? biasp : biasa;
    const float* resid = pp ? residp : resida;
    float* C = pp ? Cp : Ca;
    const int M = pp ? Mp : Ma;
    const int nid = pp ? 1 : 0;
    const int ns = pp ? 16 : 8;

    const int w = tid >> 5, ln = tid & 31;
    const int rowb = (w >> 2) * 64, colb = (w & 3) * 32;
    const int lg = ln >> 2, lt = ln & 3;

    __half* const Ab[2] = {smh, smh + SLABH};
    __half* const Bb[2] = {smh + 2 * SLABH, smh + 3 * SLABH};

    float c[4][4][4];
#pragma unroll
    for (int mi = 0; mi < 4; mi++)
#pragma unroll
        for (int ni = 0; ni < 4; ni++)
#pragma unroll
            for (int r = 0; r < 4; r++) c[mi][ni][r] = 0.f;

    auto load_slab = [&](int s, int b) {
        const __half* A;
        const __half* B;
        int k0;
        if (!pp) { A = Aa; B = Ba; k0 = s * 32; }
        else if (s < 8) { A = Ap1; B = Bp1; k0 = s * 32; }
        else { A = Ap2; B = Bp2; k0 = (s - 8) * 32; }
        __half* As = Ab[b];
        __half* Bs = Bb[b];
#pragma unroll
        for (int i = 0; i < 2; i++) {
            int idx = tid + i * 256;
            int row = idx >> 2, kg = idx & 3;
            uint32_t da = (uint32_t)__cvta_generic_to_shared(As + row * 40 + kg * 8);
            const __half* ga = A + (size_t)(m0 + row) * DD + k0 + kg * 8;
            int sz = ((m0 + row) < M) ? 16 : 0;
            asm volatile("cp.async.cg.shared.global [%0], [%1], 16, %2;\n" ::"r"(da), "l"(ga), "r"(sz));
            uint32_t db = (uint32_t)__cvta_generic_to_shared(Bs + row * 40 + kg * 8);
            const __half* gb = B + (size_t)(col0 + row) * DD + k0 + kg * 8;
            asm volatile("cp.async.cg.shared.global [%0], [%1], 16;\n" ::"r"(db), "l"(gb));
        }
        asm volatile("cp.async.commit_group;\n");
    };

    load_slab(0, 0);
    for (int s = 0; s < ns; s++) {
        int b = s & 1;
        if (s < ns - 1) {
            load_slab(s + 1, b ^ 1);
            asm volatile("cp.async.wait_group 1;\n");
        } else {
            asm volatile("cp.async.wait_group 0;\n");
        }
        __syncthreads();
        const __half* As = Ab[b];
        const __half* Bs = Bb[b];
#pragma unroll
        for (int ks = 0; ks < 2; ks++) {
            const int kk = ks * 16 + 2 * lt;
            uint32_t af[4][4], bf[4][2];
#pragma unroll
            for (int mi = 0; mi < 4; mi++) {
                const __half* p = As + (rowb + mi * 16 + lg) * 40 + kk;
                af[mi][0] = *(const uint32_t*)p;
                af[mi][1] = *(const uint32_t*)(p + 8 * 40);
                af[mi][2] = *(const uint32_t*)(p + 8);
                af[mi][3] = *(const uint32_t*)(p + 8 * 40 + 8);
            }
#pragma unroll
            for (int ni = 0; ni < 4; ni++) {
                const __half* p = Bs + (colb + ni * 8 + lg) * 40 + kk;
                bf[ni][0] = *(const uint32_t*)p;
                bf[ni][1] = *(const uint32_t*)(p + 8);
            }
#pragma unroll
            for (int mi = 0; mi < 4; mi++)
#pragma unroll
                for (int ni = 0; ni < 4; ni++) mmah(c[mi][ni], af[mi], bf[ni]);
        }
        __syncthreads();
    }

    float sv = skipv[nid];
    float alpha = 1.f / (1.f + __expf(-sv));
    float beta = 1.f - alpha;
#pragma unroll
    for (int mi = 0; mi < 4; mi++) {
#pragma unroll
        for (int half = 0; half < 2; half++) {
            int row = m0 + rowb + mi * 16 + lg + half * 8;
            if (row >= M) continue;
#pragma unroll
            for (int ni = 0; ni < 4; ni++) {
                int cc = col0 + colb + ni * 8 + lt * 2;
                float2 o;
                o.x = c[mi][ni][half * 2 + 0] + bias[cc];
                o.y = c[mi][ni][half * 2 + 1] + bias[cc + 1];
                float2 rv = *(const float2*)(resid + (size_t)row * DD + cc);
                o.x = o.x * alpha + rv.x * beta;
                o.y = o.y * alpha + rv.y * beta;
                *(float2*)(C + (size_t)row * DD + cc) = o;
            }
        }
    }
}

// ---------------- Qpc GEMM fused with edge scatter (independent regions) ----------------
__global__ __launch_bounds__(256) void gemmq_sc(
    int gBlocks, int gpB,
    const __half* __restrict__ A, const __half* __restrict__ B,
    const float* __restrict__ bias, float* __restrict__ C, int M,
    const int* __restrict__ sw, const int* __restrict__ dw,
    const int* __restrict__ sc, const int* __restrict__ dc,
    const int* __restrict__ sb, const int* __restrict__ db, int E,
    int* __restrict__ c0, int* __restrict__ c1, int* __restrict__ c2,
    int* __restrict__ col0, int* __restrict__ col1, int* __restrict__ col2) {
    extern __shared__ __half smh[];
    if ((int)blockIdx.x >= gBlocks) {
        int i = ((int)blockIdx.x - gBlocks) * 256 + threadIdx.x;
        if (i < E) { int p = atomicAdd(&c0[dw[i]], 1); col0[p] = sw[i]; }
        else if (i < 2 * E) { int j = i - E; int p = atomicAdd(&c1[dc[j]], 1); col1[p] = sc[j]; }
        else if (i < 3 * E) { int j = i - 2 * E; int p = atomicAdd(&c2[db[j]], 1); col2[p] = sb[j]; }
        return;
    }
    const int tid = threadIdx.x;
    const int m0 = ((int)blockIdx.x % gpB) * 128;
    const int col0g = ((int)blockIdx.x / gpB) * 128;
    const int w = tid >> 5, ln = tid & 31;
    const int rowb = (w >> 2) * 64, colb = (w & 3) * 32;
    const int lg = ln >> 2, lt = ln & 3;

    __half* const Ab[2] = {smh, smh + SLABH};
    __half* const Bb[2] = {smh + 2 * SLABH, smh + 3 * SLABH};

    float c[4][4][4];
#pragma unroll
    for (int mi = 0; mi < 4; mi++)
#pragma unroll
        for (int ni = 0; ni < 4; ni++)
#pragma unroll
            for (int r = 0; r < 4; r++) c[mi][ni][r] = 0.f;

    auto load_slab = [&](int s, int b) {
        const int k0 = s * 32;
        __half* As = Ab[b];
        __half* Bs = Bb[b];
#pragma unroll
        for (int i = 0; i < 2; i++) {
            int idx = tid + i * 256;
            int row = idx >> 2, kg = idx & 3;
            uint32_t da = (uint32_t)__cvta_generic_to_shared(As + row * 40 + kg * 8);
            const __half* ga = A + (size_t)(m0 + row) * DD + k0 + kg * 8;
            int sz = ((m0 + row) < M) ? 16 : 0;
            asm volatile("cp.async.cg.shared.global [%0], [%1], 16, %2;\n" ::"r"(da), "l"(ga), "r"(sz));
            uint32_t dbs = (uint32_t)__cvta_generic_to_shared(Bs + row * 40 + kg * 8);
            const __half* gb = B + (size_t)(col0g + row) * DD + k0 + kg * 8;
            asm volatile("cp.async.cg.shared.global [%0], [%1], 16;\n" ::"r"(dbs), "l"(gb));
        }
        asm volatile("cp.async.commit_group;\n");
    };

    load_slab(0, 0);
    for (int s = 0; s < 8; s++) {
        int b = s & 1;
        if (s < 7) {
            load_slab(s + 1, b ^ 1);
            asm volatile("cp.async.wait_group 1;\n");
        } else {
            asm volatile("cp.async.wait_group 0;\n");
        }
        __syncthreads();
        const __half* As = Ab[b];
        const __half* Bs = Bb[b];
#pragma unroll
        for (int ks = 0; ks < 2; ks++) {
            const int kk = ks * 16 + 2 * lt;
            uint32_t af[4][4], bf[4][2];
#pragma unroll
            for (int mi = 0; mi < 4; mi++) {
                const __half* p = As + (rowb + mi * 16 + lg) * 40 + kk;
                af[mi][0] = *(const uint32_t*)p;
                af[mi][1] = *(const uint32_t*)(p + 8 * 40);
                af[mi][2] = *(const uint32_t*)(p + 8);
                af[mi][3] = *(const uint32_t*)(p + 8 * 40 + 8);
            }
#pragma unroll
            for (int ni = 0; ni < 4; ni++) {
                const __half* p = Bs + (colb + ni * 8 + lg) * 40 + kk;
                bf[ni][0] = *(const uint32_t*)p;
                bf[ni][1] = *(const uint32_t*)(p + 8);
            }
#pragma unroll
            for (int mi = 0; mi < 4; mi++)
#pragma unroll
                for (int ni = 0; ni < 4; ni++) mmah(c[mi][ni], af[mi], bf[ni]);
        }
        __syncthreads();
    }

#pragma unroll
    for (int mi = 0; mi < 4; mi++) {
#pragma unroll
        for (int half = 0; half < 2; half++) {
            int row = m0 + rowb + mi * 16 + lg + half * 8;
            if (row >= M) continue;
#pragma unroll
            for (int ni = 0; ni < 4; ni++) {
                int cc = col0g + colb + ni * 8 + lt * 2;
                float2 o;
                o.x = c[mi][ni][half * 2 + 0] + bias[cc];
                o.y = c[mi][ni][half * 2 + 1] + bias[cc + 1];
                *(float2*)(C + (size_t)row * DD + cc) = o;
            }
        }
    }
}

// ---------------- fused fp16 3-B projection GEMM ----------------
__global__ __launch_bounds__(256, 1) void gemm3h(
    int gaBlocks,
    const __half* __restrict__ Aa, const __half* __restrict__ Ap,
    const __half* __restrict__ Ba0, const __half* __restrict__ Ba1, const __half* __restrict__ Ba2,
    const __half* __restrict__ Bp0, const __half* __restrict__ Bp1, const __half* __restrict__ Bp2,
    const float* __restrict__ ba0, const float* __restrict__ ba1, const float* __restrict__ ba2,
    const float* __restrict__ bp0, const float* __restrict__ bp1, const float* __restrict__ bp2,
    __half* __restrict__ CaK, __half* __restrict__ CaV, float* __restrict__ CaQ,
    __half* __restrict__ CpK, __half* __restrict__ CpV, float* __restrict__ CpQ,
    int Ma, int Mp) {
    extern __shared__ __half smh[];
    const int tid = threadIdx.x;
    const bool pp = (int)blockIdx.x >= gaBlocks;
    const int m0 = ((int)blockIdx.x - (pp ? gaBlocks : 0)) * 128;
    const int col0 = blockIdx.y * 128;
    const __half* A = pp ? Ap : Aa;
    const int M = pp ? Mp : Ma;
    const __half* const Bv[3] = {pp ? Bp0 : Ba0, pp ? Bp1 : Ba1, pp ? Bp2 : Ba2};
    const float* const biv[3] = {pp ? bp0 : ba0, pp ? bp1 : ba1, pp ? bp2 : ba2};
    __half* const Chv[2] = {pp ? CpK : CaK, pp ? CpV : CaV};
    float* const Cq = pp ? CpQ : CaQ;

    const int w = tid >> 5, ln = tid & 31;
    const int rowb = (w >> 2) * 64, colb = (w & 3) * 32;
    const int lg = ln >> 2, lt = ln & 3;

    float c[3][4][4][4];
#pragma unroll
    for (int b = 0; b < 3; b++)
#pragma unroll
        for (int mi = 0; mi < 4; mi++)
#pragma unroll
            for (int ni = 0; ni < 4; ni++)
#pragma unroll
                for (int r = 0; r < 4; r++) c[b][mi][ni][r] = 0.f;

    auto load_slab = [&](int s, int buf) {
        const int k0 = s * 32;
        __half* As = smh + buf * SLABH;
#pragma unroll
        for (int i = 0; i < 2; i++) {
            int idx = tid + i * 256;
            int row = idx >> 2, kg = idx & 3;
            uint32_t da = (uint32_t)__cvta_generic_to_shared(As + row * 40 + kg * 8);
            const __half* ga = A + (size_t)(m0 + row) * DD + k0 + kg * 8;
            int sz = ((m0 + row) < M) ? 16 : 0;
            asm volatile("cp.async.cg.shared.global [%0], [%1], 16, %2;\n" ::"r"(da), "l"(ga), "r"(sz));
        }
#pragma unroll
        for (int b = 0; b < 3; b++) {
            __half* Bs = smh + (2 + b * 2 + buf) * SLABH;
#pragma unroll
            for (int i = 0; i < 2; i++) {
                int idx = tid + i * 256;
                int row = idx >> 2, kg = idx & 3;
                uint32_t db = (uint32_t)__cvta_generic_to_shared(Bs + row * 40 + kg * 8);
                const __half* gb = Bv[b] + (size_t)(col0 + row) * DD + k0 + kg * 8;
                asm volatile("cp.async.cg.shared.global [%0], [%1], 16;\n" ::"r"(db), "l"(gb));
            }
        }
        asm volatile("cp.async.commit_group;\n");
    };

    load_slab(0, 0);
    for (int s = 0; s < 8; s++) {
        int buf = s & 1;
        if (s < 7) {
            load_slab(s + 1, buf ^ 1);
            asm volatile("cp.async.wait_group 1;\n");
        } else {
            asm volatile("cp.async.wait_group 0;\n");
        }
        __syncthreads();
        const __half* As = smh + buf * SLABH;
#pragma unroll
        for (int ks = 0; ks < 2; ks++) {
            const int kk = ks * 16 + 2 * lt;
            uint32_t af[4][4];
#pragma unroll
            for (int mi = 0; mi < 4; mi++) {
                const __half* p = As + (rowb + mi * 16 + lg) * 40 + kk;
                af[mi][0] = *(const uint32_t*)p;
                af[mi][1] = *(const uint32_t*)(p + 8 * 40);
                af[mi][2] = *(const uint32_t*)(p + 8);
                af[mi][3] = *(const uint32_t*)(p + 8 * 40 + 8);
            }
#pragma unroll
            for (int b = 0; b < 3; b++) {
                const __half* Bs = smh + (2 + b * 2 + buf) * SLABH;
                uint32_t bf[4][2];
#pragma unroll
                for (int ni = 0; ni < 4; ni++) {
                    const __half* p = Bs + (colb + ni * 8 + lg) * 40 + kk;
                    bf[ni][0] = *(const uint32_t*)p;
                    bf[ni][1] = *(const uint32_t*)(p + 8);
                }
#pragma unroll
                for (int mi = 0; mi < 4; mi++)
#pragma unroll
                    for (int ni = 0; ni < 4; ni++) mmah(c[b][mi][ni], af[mi], bf[ni]);
            }
        }
        __syncthreads();
    }

#pragma unroll
    for (int b = 0; b < 3; b++) {
#pragma unroll
        for (int mi = 0; mi < 4; mi++) {
#pragma unroll
            for (int half = 0; half < 2; half++) {
                int row = m0 + rowb + mi * 16 + lg + half * 8;
                if (row >= M) continue;
#pragma unroll
                for (int ni = 0; ni < 4; ni++) {
                    int cc = col0 + colb + ni * 8 + lt * 2;
                    float ox = c[b][mi][ni][half * 2 + 0] + biv[b][cc];
                    float oy = c[b][mi][ni][half * 2 + 1] + biv[b][cc + 1];
                    if (b < 2) {
                        *(__half2*)(Chv[b] + (size_t)row * DD + cc) = __floats2half2_rn(ox, oy);
                    } else {
                        *(float2*)(Cq + (size_t)row * DD + cc) = make_float2(ox, oy);
                    }
                }
            }
        }
    }
}

// ---------------- CSR scan (wide, scanB inlined into scanC) ----------------
#define BLKE 2048
#define NB0 25
#define NB1 25
#define NB2 10

__device__ __forceinline__ void seg_of(int b, const int** deg, int* base, int* n, int* lb,
                                       const int* d0, const int* d1, const int* d2) {
    if (b < NB0) { *deg = d0; *lb = b; *n = NP; }
    else if (b < NB0 + NB1) { *deg = d1; *lb = b - NB0; *n = NP; }
    else { *deg = d2; *lb = b - NB0 - NB1; *n = NA; }
    *base = *lb * BLKE;
}

__global__ void scanA(const int* __restrict__ d0, const int* __restrict__ d1,
                      const int* __restrict__ d2, int* __restrict__ psum) {
    __shared__ int sh[512];
    const int* deg; int base, n, lb;
    seg_of(blockIdx.x, &deg, &base, &n, &lb, d0, d1, d2);
    int t = threadIdx.x;
    int s = 0;
#pragma unroll
    for (int k = 0; k < 4; k++) {
        int i = base + t * 4 + k;
        if (i < n && t * 4 + k < BLKE) s += deg[i];
    }
    sh[t] = s;
    __syncthreads();
    for (int off = 256; off; off >>= 1) {
        if (t < off) sh[t] += sh[t + off];
        __syncthreads();
    }
    if (t == 0) psum[blockIdx.x] = sh[0];
}

__global__ void scanC(const int* __restrict__ d0, const int* __restrict__ d1,
                      const int* __restrict__ d2, const int* __restrict__ psum,
                      int* __restrict__ rp0, int* __restrict__ rp1, int* __restrict__ rp2,
                      int* __restrict__ c0, int* __restrict__ c1, int* __restrict__ c2) {
    __shared__ int sh[512];
    __shared__ int pb;
    const int* deg; int base, n, lb;
    seg_of(blockIdx.x, &deg, &base, &n, &lb, d0, d1, d2);
    int* rp; int* cur;
    int segstart;
    if (blockIdx.x < NB0) { rp = rp0; cur = c0; segstart = 0; }
    else if (blockIdx.x < NB0 + NB1) { rp = rp1; cur = c1; segstart = NB0; }
    else { rp = rp2; cur = c2; segstart = NB0 + NB1; }
    int t = threadIdx.x;
    if (t < 32) {
        int v = (t < lb) ? psum[segstart + t] : 0;
#pragma unroll
        for (int o = 16; o; o >>= 1) v += __shfl_xor_sync(0xffffffffu, v, o);
        if (t == 0) pb = v;
    }
    int v[4];
    int loc = 0;
#pragma unroll
    for (int k = 0; k < 4; k++) {
        int i = base + t * 4 + k;
        v[k] = (i < n) ? deg[i] : 0;
        loc += v[k];
    }
    sh[t] = loc;
    __syncthreads();
    for (int off = 1; off < 512; off <<= 1) {
        int x = (t >= off) ? sh[t - off] : 0;
        __syncthreads();
        sh[t] += x;
        __syncthreads();
    }
    int pre = (t ? sh[t - 1] : 0) + pb;
#pragma unroll
    for (int k = 0; k < 4; k++) {
        int i = base + t * 4 + k;
        if (i < n) {
            cur[i] = pre;
            pre += v[k];
            rp[i + 1] = pre;
        }
    }
    if (lb == 0 && t == 0) rp[0] = 0;
}

// ---------------- aggregation with fp16 K/V gathers; all outputs fp16 ----------------
__device__ __forceinline__ void csr_attend8h(
    int node, int lane, const int* __restrict__ rp, const int* __restrict__ colv,
    const __half* __restrict__ K, const __half* __restrict__ V,
    const float4 qa, const float4 qb, const float prih, float acc[8]) {
    float s = 0.f;
    float a[8];
#pragma unroll
    for (int j = 0; j < 8; j++) a[j] = 0.f;
    const int off = (lane >> 2) * DKH + (lane & 3) * 8;
    const int beg = rp[node], end = rp[node + 1];
    for (int e = beg; e < end; e++) {
        const int src = colv[e];
        uint4 kq = *(const uint4*)(K + (size_t)src * DD + off);
        const __half2* kh = (const __half2*)&kq;
        float2 k0 = __half22float2(kh[0]);
        float2 k1 = __half22float2(kh[1]);
        float2 k2 = __half22float2(kh[2]);
        float2 k3 = __half22float2(kh[3]);
        float p = qa.x * k0.x + qa.y * k0.y + qa.z * k1.x + qa.w * k1.y +
                  qb.x * k2.x + qb.y * k2.y + qb.z * k3.x + qb.w * k3.y;
        p += __shfl_xor_sync(0xffffffffu, p, 1);
        p += __shfl_xor_sync(0xffffffffu, p, 2);
        float wgt = __expf(p * prih);
        uint4 vq = *(const uint4*)(V + (size_t)src * DD + off);
        const __half2* vh = (const __half2*)&vq;
        float2 v0 = __half22float2(vh[0]);
        float2 v1 = __half22float2(vh[1]);
        float2 v2 = __half22float2(vh[2]);
        float2 v3 = __half22float2(vh[3]);
        s += wgt;
        a[0] += wgt * v0.x; a[1] += wgt * v0.y; a[2] += wgt * v1.x; a[3] += wgt * v1.y;
        a[4] += wgt * v2.x; a[5] += wgt * v2.y; a[6] += wgt * v3.x; a[7] += wgt * v3.y;
    }
    if (s > 0.f) {
        float inv = 1.f / s;
#pragma unroll
        for (int j = 0; j < 8; j++) acc[j] += a[j] * inv;
    }
}

__device__ __forceinline__ void store_h8(__half* dst, const float acc[8]) {
    __half2 h0 = __floats2half2_rn(acc[0], acc[1]);
    __half2 h1 = __floats2half2_rn(acc[2], acc[3]);
    __half2 h2 = __floats2half2_rn(acc[4], acc[5]);
    __half2 h3 = __floats2half2_rn(acc[6], acc[7]);
    uint4 o;
    o.x = *(uint32_t*)&h0; o.y = *(uint32_t*)&h1; o.z = *(uint32_t*)&h2; o.w = *(uint32_t*)&h3;
    *(uint4*)dst = o;
}

__global__ void agg_all(const float* __restrict__ Qp, const float* __restrict__ Qpc,
                        const float* __restrict__ Qa,
                        const __half* __restrict__ K0, const __half* __restrict__ V0,
                        const __half* __restrict__ Kp, const __half* __restrict__ Vp,
                        const int* __restrict__ rp0, const int* __restrict__ col0,
                        const int* __restrict__ rp1, const int* __restrict__ col1,
                        const int* __restrict__ rp2, const int* __restrict__ col2,
                        const float* __restrict__ rel_pri,
                        __half* __restrict__ aggw, __half* __restrict__ aggc,
                        __half* __restrict__ agga) {
    int w = (blockIdx.x * blockDim.x + threadIdx.x) >> 5;
    int lane = threadIdx.x & 31;
    const float sc = 0.17677669529663687f;
    const int h = lane >> 2;
    const int off = h * DKH + (lane & 3) * 8;
    if (w < NP) {
        const size_t qoff = (size_t)w * DD + off;
        {
            float4 qa = *(const float4*)(Qp + qoff);
            float4 qb = *(const float4*)(Qp + qoff + 4);
            float acc[8];
#pragma unroll
            for (int j = 0; j < 8; j++) acc[j] = 0.f;
            csr_attend8h(w, lane, rp0, col0, K0, V0, qa, qb, rel_pri[h] * sc, acc);
            store_h8(aggw + qoff, acc);
        }
        {
            float4 qa = *(const float4*)(Qpc + qoff);
            float4 qb = *(const float4*)(Qpc + qoff + 4);
            float acc[8];
#pragma unroll
            for (int j = 0; j < 8; j++) acc[j] = 0.f;
            csr_attend8h(w, lane, rp1, col1, Kp, Vp, qa, qb, rel_pri[NH + h] * sc, acc);
            store_h8(aggc + qoff, acc);
        }
    } else if (w < NP + NA) {
        int n = w - NP;
        const size_t qoff = (size_t)n * DD + off;
        float4 qa = *(const float4*)(Qa + qoff);
        float4 qb = *(const float4*)(Qa + qoff + 4);
        float acc[8];
#pragma unroll
        for (int j = 0; j < 8; j++) acc[j] = 0.f;
        csr_attend8h(n, lane, rp2, col2, Kp, Vp, qa, qb, rel_pri[2 * NH + h] * sc, acc);
        store_h8(agga + qoff, acc);
    }
}

// ---------------- host launch ----------------
extern "C" void kernel_launch(void* const* d_in, const int* in_sizes, int n_in,
                              void* d_out, int out_size) {
    const float* h_author = (const float*)d_in[0];
    const float* h_paper  = (const float*)d_in[1];
    const float* k_w  = (const float*)d_in[2];
    const float* k_b  = (const float*)d_in[3];
    const float* q_w  = (const float*)d_in[4];
    const float* q_b  = (const float*)d_in[5];
    const float* v_w  = (const float*)d_in[6];
    const float* v_b  = (const float*)d_in[7];
    const float* a_w  = (const float*)d_in[8];
    const float* a_b  = (const float*)d_in[9];
    const float* rel_att = (const float*)d_in[10];
    const float* rel_msg = (const float*)d_in[11];
    const float* rel_pri = (const float*)d_in[12];
    const float* skipv   = (const float*)d_in[13];
    const int* src_writes = (const int*)d_in[14];
    const int* dst_writes = (const int*)d_in[15];
    const int* src_cites  = (const int*)d_in[16];
    const int* dst_cites  = (const int*)d_in[17];
    const int* src_wb     = (const int*)d_in[18];
    const int* dst_wb     = (const int*)d_in[19];

    int E = in_sizes[14];
    if (E > EMAX) E = EMAX;

    __half *Har, *Hpr, *K0, *V0, *Kp, *Vp, *aggPw, *aggPc, *aggAc, *fW, *rw;
    float *Qa, *Qp, *Qpc, *fB;
    int *deg0, *deg1, *deg2, *rp0, *rp1, *rp2, *cur0, *cur1, *cur2, *col0, *col1, *col2;
    int *psum;
    cudaGetSymbolAddress((void**)&Har, g_Har);
    cudaGetSymbolAddress((void**)&Hpr, g_Hpr);
    cudaGetSymbolAddress((void**)&K0, g_K0);
    cudaGetSymbolAddress((void**)&V0, g_V0);
    cudaGetSymbolAddress((void**)&Qa, g_Qa);
    cudaGetSymbolAddress((void**)&Kp, g_Kp);
    cudaGetSymbolAddress((void**)&Vp, g_Vp);
    cudaGetSymbolAddress((void**)&Qp, g_Qp);
    cudaGetSymbolAddress((void**)&Qpc, g_Qpc);
    cudaGetSymbolAddress((void**)&aggPw, g_aggPw);
    cudaGetSymbolAddress((void**)&aggPc, g_aggPc);
    cudaGetSymbolAddress((void**)&aggAc, g_aggAc);
    cudaGetSymbolAddress((void**)&fW, g_fW);
    cudaGetSymbolAddress((void**)&fB, g_fB);
    cudaGetSymbolAddress((void**)&rw, g_rw);
    cudaGetSymbolAddress((void**)&deg0, g_deg0);
    cudaGetSymbolAddress((void**)&deg1, g_deg1);
    cudaGetSymbolAddress((void**)&deg2, g_deg2);
    cudaGetSymbolAddress((void**)&rp0, g_rp0);
    cudaGetSymbolAddress((void**)&rp1, g_rp1);
    cudaGetSymbolAddress((void**)&rp2, g_rp2);
    cudaGetSymbolAddress((void**)&cur0, g_cur0);
    cudaGetSymbolAddress((void**)&cur1, g_cur1);
    cudaGetSymbolAddress((void**)&cur2, g_cur2);
    cudaGetSymbolAddress((void**)&col0, g_col0);
    cudaGetSymbolAddress((void**)&col1, g_col1);
    cudaGetSymbolAddress((void**)&col2, g_col2);
    cudaGetSymbolAddress((void**)&psum, g_psum);

    cudaFuncSetAttribute(gemm_out, cudaFuncAttributeMaxDynamicSharedMemorySize, GSO);
    cudaFuncSetAttribute(gemmq_sc, cudaFuncAttributeMaxDynamicSharedMemorySize, GSO);
    cudaFuncSetAttribute(gemm3h, cudaFuncAttributeMaxDynamicSharedMemorySize, GS3H);

    __half* kwr1 = rw + 0 * 65536;
    __half* vwr1 = rw + 1 * 65536;
    __half* qwr1 = rw + 2 * 65536;
    __half* awp  = rw + 3 * 65536;
    __half* fWk0 = fW + 0 * 65536;
    __half* fWv0 = fW + 1 * 65536;
    __half* fWqa = fW + 2 * 65536;
    __half* fWaw = fW + 3 * 65536;
    __half* fWqc = fW + 4 * 65536;
    __half* fWac = fW + 5 * 65536;
    float* fBk0 = fB + 0 * 256;
    float* fBv0 = fB + 1 * 256;
    float* fBqa = fB + 2 * 256;
    float* fBqc = fB + 3 * 256;

    // 1) fused conversions + degree zeroing
    {
        int n0 = NA * DD / 8, n1 = NP * DD / 8, n2 = 65536 / 8, n3 = 65536 / 8,
            n4 = 65536 / 8, n5 = 65536 / 8;
        int total = n0 + n1 + n2 + n3 + n4 + n5 + (NP + NA);
        halfcopy_zero<<<(total + 255) / 256, 256>>>(
            h_author, Har, n0, h_paper, Hpr, n1,
            k_w + 65536, kwr1, n2, v_w + 65536, vwr1, n3,
            q_w + 65536, qwr1, n4, a_w + 65536, awp, n5,
            deg0, deg1, deg2);
    }

    // 2) fused weight folds + edge histogram
    {
        int hb = (3 * E + 255) / 256;
        fold_hist<<<1536 + hb, 256>>>(k_w, v_w, q_w, a_w, k_b, v_b, q_b, rel_att, rel_msg,
                                      fWk0, fWv0, fWqa, fWaw, fWqc, fWac,
                                      fBk0, fBv0, fBqa, fBqc,
                                      dst_writes, dst_cites, dst_wb, E, deg0, deg1, deg2);
    }

    // 3) fused fp16 projection GEMM
    const int gaB = (NA + 127) / 128, gpB = (NP + 127) / 128;
    {
        dim3 g(gaB + gpB, 2);
        gemm3h<<<g, 256, GS3H>>>(gaB, Har, Hpr,
                                 fWk0, fWv0, fWqa, kwr1, vwr1, qwr1,
                                 fBk0, fBv0, fBqa, k_b + 256, v_b + 256, q_b + 256,
                                 K0, V0, Qa, Kp, Vp, Qp, NA, NP);
    }

    // 4) CSR scans (scanB inlined into scanC)
    scanA<<<NB0 + NB1 + NB2, 512>>>(deg0, deg1, deg2, psum);
    scanC<<<NB0 + NB1 + NB2, 512>>>(deg0, deg1, deg2, psum, rp0, rp1, rp2, cur0, cur1, cur2);

    // 5) Qpc GEMM fused with edge scatter
    {
        int gB = gpB * 2;
        int sb = (3 * E + 255) / 256;
        gemmq_sc<<<gB + sb, 256, GSO>>>(gB, gpB, Hpr, fWqc, fBqc, Qpc, NP,
                                        src_writes, dst_writes, src_cites, dst_cites,
                                        src_wb, dst_wb, E, cur0, cur1, cur2,
                                        col0, col1, col2);
    }

    // 6) fused aggregation
    agg_all<<<((NP + NA) * 32 + 255) / 256, 256>>>(Qp, Qpc, Qa, K0, V0, Kp, Vp,
                                                   rp0, col0, rp1, col1, rp2, col2,
                                                   rel_pri, aggPw, aggPc, aggAc);

    // 7) fused output GEMM
    float* out = (float*)d_out;
    {
        dim3 g(gaB + gpB, 2);
        gemm_out<<<g, 256, GSO>>>(gaB, aggAc, fWaw, aggPw, awp, aggPc, fWac,
                                  a_b, a_b + 256, h_author, h_paper, skipv,
                                  out, out + (size_t)NA * DD, NA, NP);
    }
}